// round 2
// baseline (speedup 1.0000x reference)
#include <cuda_runtime.h>
#include <math.h>

// Problem constants (fixed shapes from the reference)
#define N_ENT   14541
#define N_REL   237
#define M_EDGES 272115
#define D       256
#define BS      16
#define NT      4          // entities per warp tile

// Scratch (no cudaMalloc allowed): sig[n][b] and per-relation batch bitmask
__device__ float    g_sig[N_ENT * BS];
__device__ unsigned g_relmask[N_REL];

// ---------------------------------------------------------------------------
// prep: build per-relation 16-bit batch-match bitmask
// ---------------------------------------------------------------------------
__global__ void prep_kernel(const int* __restrict__ relation_ids) {
    int r = blockIdx.x * blockDim.x + threadIdx.x;
    if (r < N_REL) {
        unsigned m = 0;
        #pragma unroll
        for (int b = 0; b < BS; b++)
            m |= (relation_ids[b] == r) ? (1u << b) : 0u;
        g_relmask[r] = m;
    }
}

// ---------------------------------------------------------------------------
// dist: sig[n][b] = sigmoid(12 - sum_d |rel[b,d]| * |emb[b,d] - all_emb[n,d]|)
//       with sig[source_idx[b]][b] = 0 (sigmoid(12-1e8) == 0 in fp32)
// One warp handles NT=4 entities. Lane owns d in {4L..4L+3} u {128+4L..128+4L+3}.
// ---------------------------------------------------------------------------
__global__ void __launch_bounds__(256) dist_kernel(
    const float* __restrict__ emb,
    const float* __restrict__ all_emb,
    const float* __restrict__ tail_r,
    const int*   __restrict__ source_idx,
    const int*   __restrict__ relation_ids)
{
    __shared__ float es[BS * D];   // emb[b][d]
    __shared__ float rs[BS * D];   // |tail_r[relation_ids[b]][d]|
    __shared__ int   s_src[BS];

    const int tid  = threadIdx.x;
    const int lane = tid & 31;

    if (tid < BS) s_src[tid] = source_idx[tid];
    for (int i = tid; i < BS * D; i += 256) {
        int b = i >> 8;          // i / D
        int d = i & (D - 1);     // i % D
        es[i] = emb[i];
        rs[i] = fabsf(tail_r[relation_ids[b] * D + d]);
    }
    __syncthreads();

    const int warp = blockIdx.x * 8 + (tid >> 5);
    const int n0   = warp * NT;
    if (n0 >= N_ENT) return;
    const bool full_tile = (n0 + NT <= N_ENT);

    // Preload all_emb rows for this tile (coalesced LDG.128)
    float4 xl[NT], xh[NT];
    if (full_tile) {
        #pragma unroll
        for (int n = 0; n < NT; n++) {
            const float4* row = (const float4*)(all_emb + (n0 + n) * D);
            xl[n] = row[lane];
            xh[n] = row[32 + lane];
        }
    } else {
        #pragma unroll
        for (int n = 0; n < NT; n++) {
            int nn = n0 + n; if (nn >= N_ENT) nn = N_ENT - 1;
            const float4* row = (const float4*)(all_emb + nn * D);
            xl[n] = row[lane];
            xh[n] = row[32 + lane];
        }
    }

    float acc[NT * BS];
    #pragma unroll
    for (int i = 0; i < NT * BS; i++) acc[i] = 0.f;

    const float4* es4 = (const float4*)es;
    const float4* rs4 = (const float4*)rs;

    #pragma unroll
    for (int b = 0; b < BS; b++) {
        float4 e0 = es4[b * 64 + lane];
        float4 e1 = es4[b * 64 + 32 + lane];
        float4 r0 = rs4[b * 64 + lane];
        float4 r1 = rs4[b * 64 + 32 + lane];
        #pragma unroll
        for (int n = 0; n < NT; n++) {
            float s = acc[n * BS + b];
            s += r0.x * fabsf(e0.x - xl[n].x);
            s += r0.y * fabsf(e0.y - xl[n].y);
            s += r0.z * fabsf(e0.z - xl[n].z);
            s += r0.w * fabsf(e0.w - xl[n].w);
            s += r1.x * fabsf(e1.x - xh[n].x);
            s += r1.y * fabsf(e1.y - xh[n].y);
            s += r1.z * fabsf(e1.z - xh[n].z);
            s += r1.w * fabsf(e1.w - xh[n].w);
            acc[n * BS + b] = s;
        }
    }

    // Value-splitting butterfly: reduce 64 partial sums across 32 lanes in
    // 62 shuffles. After 5 steps lane L holds flat sums f = 2L and 2L+1,
    // where f = n_local*16 + b.
    #pragma unroll
    for (int step = 0; step < 5; step++) {
        const int mask = 16 >> step;
        const int V    = 64 >> step;
        const bool hi  = (lane & mask) != 0;
        #pragma unroll
        for (int i = 0; i < V / 2; i++) {
            float send = hi ? acc[i]         : acc[i + V / 2];
            float keep = hi ? acc[i + V / 2] : acc[i];
            float other = __shfl_xor_sync(0xffffffffu, send, mask);
            acc[i] = keep + other;
        }
    }

    // Epilogue: mask + sigmoid, coalesced float2 store
    const int f  = 2 * lane;
    const int nn = n0 + (f >> 4);
    const int b  = f & 15;
    if (nn < N_ENT) {
        float s0 = 1.0f / (1.0f + expf(acc[0] - 12.0f));
        float s1 = 1.0f / (1.0f + expf(acc[1] - 12.0f));
        if (nn == s_src[b])     s0 = 0.0f;
        if (nn == s_src[b + 1]) s1 = 0.0f;
        *(float2*)(g_sig + nn * BS + b) = make_float2(s0, s1);
    }
}

// ---------------------------------------------------------------------------
// edge: for each edge, if its relation matches any batch relation, gather
// sig[head][b] and atomically scatter onto out[b][tail]. ~93% of edges match
// nothing and exit after one bitmask load.
// ---------------------------------------------------------------------------
__device__ __forceinline__ void process_edge(int h, int t, int r,
                                             float* __restrict__ out) {
    unsigned m = g_relmask[r];
    while (m) {
        int b = __ffs(m) - 1;
        m &= m - 1;
        atomicAdd(out + b * N_ENT + t, g_sig[h * BS + b]);
    }
}

__global__ void edge_kernel(const int* __restrict__ heads,
                            const int* __restrict__ tails,
                            const int* __restrict__ rels,
                            float* __restrict__ out)
{
    const int i    = blockIdx.x * blockDim.x + threadIdx.x;
    const int base = i * 4;
    if (base + 4 <= M_EDGES) {
        int4 h4 = *(const int4*)(heads + base);
        int4 t4 = *(const int4*)(tails + base);
        int4 r4 = *(const int4*)(rels  + base);
        process_edge(h4.x, t4.x, r4.x, out);
        process_edge(h4.y, t4.y, r4.y, out);
        process_edge(h4.z, t4.z, r4.z, out);
        process_edge(h4.w, t4.w, r4.w, out);
    } else if (base < M_EDGES) {
        for (int k = base; k < M_EDGES; k++)
            process_edge(heads[k], tails[k], rels[k], out);
    }
}

// ---------------------------------------------------------------------------
extern "C" void kernel_launch(void* const* d_in, const int* in_sizes, int n_in,
                              void* d_out, int out_size) {
    const float* emb          = (const float*)d_in[0];
    const float* all_emb      = (const float*)d_in[1];
    const float* tail_r       = (const float*)d_in[2];
    const int*   source_idx   = (const int*)  d_in[3];
    const int*   relation_ids = (const int*)  d_in[4];
    const int*   heads        = (const int*)  d_in[5];
    const int*   tails        = (const int*)  d_in[6];
    const int*   edge_rels    = (const int*)  d_in[7];
    float*       out          = (float*)d_out;

    // Zero the output (scatter-add target). Graph-capturable.
    cudaMemsetAsync(out, 0, (size_t)out_size * sizeof(float));

    prep_kernel<<<1, 256>>>(relation_ids);

    const int warps  = (N_ENT + NT - 1) / NT;      // 3636
    const int blocks = (warps + 7) / 8;            // 455
    dist_kernel<<<blocks, 256>>>(emb, all_emb, tail_r, source_idx, relation_ids);

    const int ethreads = (M_EDGES + 3) / 4;        // 68029
    const int eblocks  = (ethreads + 255) / 256;   // 266
    edge_kernel<<<eblocks, 256>>>(heads, tails, edge_rels, out);
}

// round 3
// speedup vs baseline: 1.1000x; 1.1000x over previous
#include <cuda_runtime.h>
#include <math.h>

// Problem constants (fixed shapes from the reference)
#define N_ENT   14541
#define N_REL   237
#define M_EDGES 272115
#define D       256
#define BS      16
#define NT      4          // entities per warp tile
#define OUT_ELEMS (N_ENT * BS)

// Scratch (no cudaMalloc allowed): sig[n][b]
__device__ float g_sig[N_ENT * BS];

// ---------------------------------------------------------------------------
// dist: sig[n][b] = sigmoid(12 - sum_d |rel[b,d]| * |emb[b,d] - all_emb[n,d]|)
//       with sig[source_idx[b]][b] = 0 (sigmoid(12-1e8) == 0 in fp32)
// One warp handles NT=4 entities. Lane owns d in {4L..4L+3} u {128+4L..128+4L+3}.
// Also zeroes `out` (the scatter-add target for the subsequent edge kernel).
// ---------------------------------------------------------------------------
__global__ void __launch_bounds__(256) dist_kernel(
    const float* __restrict__ emb,
    const float* __restrict__ all_emb,
    const float* __restrict__ tail_r,
    const int*   __restrict__ source_idx,
    const int*   __restrict__ relation_ids,
    float*       __restrict__ out)
{
    __shared__ float es[BS * D];   // emb[b][d]
    __shared__ float rs[BS * D];   // |tail_r[relation_ids[b]][d]|
    __shared__ int   s_src[BS];

    const int tid  = threadIdx.x;
    const int lane = tid & 31;

    // Zero the output buffer (930 KB spread over 455 blocks; overlaps staging).
    {
        const int gthread = blockIdx.x * 256 + tid;
        const int i0 = gthread * 2;
        if (i0 + 2 <= OUT_ELEMS)
            *(float2*)(out + i0) = make_float2(0.f, 0.f);
        else if (i0 < OUT_ELEMS)
            out[i0] = 0.f;
    }

    if (tid < BS) s_src[tid] = source_idx[tid];
    for (int i = tid; i < BS * D; i += 256) {
        int b = i >> 8;          // i / D
        int d = i & (D - 1);     // i % D
        es[i] = emb[i];
        rs[i] = fabsf(tail_r[relation_ids[b] * D + d]);
    }
    __syncthreads();

    const int warp = blockIdx.x * 8 + (tid >> 5);
    const int n0   = warp * NT;
    if (n0 >= N_ENT) return;
    const bool full_tile = (n0 + NT <= N_ENT);

    // Preload all_emb rows for this tile (coalesced LDG.128)
    float4 xl[NT], xh[NT];
    if (full_tile) {
        #pragma unroll
        for (int n = 0; n < NT; n++) {
            const float4* row = (const float4*)(all_emb + (n0 + n) * D);
            xl[n] = row[lane];
            xh[n] = row[32 + lane];
        }
    } else {
        #pragma unroll
        for (int n = 0; n < NT; n++) {
            int nn = n0 + n; if (nn >= N_ENT) nn = N_ENT - 1;
            const float4* row = (const float4*)(all_emb + nn * D);
            xl[n] = row[lane];
            xh[n] = row[32 + lane];
        }
    }

    float acc[NT * BS];
    #pragma unroll
    for (int i = 0; i < NT * BS; i++) acc[i] = 0.f;

    const float4* es4 = (const float4*)es;
    const float4* rs4 = (const float4*)rs;

    #pragma unroll
    for (int b = 0; b < BS; b++) {
        float4 e0 = es4[b * 64 + lane];
        float4 e1 = es4[b * 64 + 32 + lane];
        float4 r0 = rs4[b * 64 + lane];
        float4 r1 = rs4[b * 64 + 32 + lane];
        #pragma unroll
        for (int n = 0; n < NT; n++) {
            float s = acc[n * BS + b];
            s += r0.x * fabsf(e0.x - xl[n].x);
            s += r0.y * fabsf(e0.y - xl[n].y);
            s += r0.z * fabsf(e0.z - xl[n].z);
            s += r0.w * fabsf(e0.w - xl[n].w);
            s += r1.x * fabsf(e1.x - xh[n].x);
            s += r1.y * fabsf(e1.y - xh[n].y);
            s += r1.z * fabsf(e1.z - xh[n].z);
            s += r1.w * fabsf(e1.w - xh[n].w);
            acc[n * BS + b] = s;
        }
    }

    // Value-splitting butterfly: reduce 64 partial sums across 32 lanes in
    // 62 shuffles. After 5 steps lane L holds flat sums f = 2L and 2L+1,
    // where f = n_local*16 + b.
    #pragma unroll
    for (int step = 0; step < 5; step++) {
        const int mask = 16 >> step;
        const int V    = 64 >> step;
        const bool hi  = (lane & mask) != 0;
        #pragma unroll
        for (int i = 0; i < V / 2; i++) {
            float send = hi ? acc[i]         : acc[i + V / 2];
            float keep = hi ? acc[i + V / 2] : acc[i];
            float other = __shfl_xor_sync(0xffffffffu, send, mask);
            acc[i] = keep + other;
        }
    }

    // Epilogue: mask + sigmoid, coalesced float2 store
    const int f  = 2 * lane;
    const int nn = n0 + (f >> 4);
    const int b  = f & 15;
    if (nn < N_ENT) {
        float s0 = 1.0f / (1.0f + expf(acc[0] - 12.0f));
        float s1 = 1.0f / (1.0f + expf(acc[1] - 12.0f));
        if (nn == s_src[b])     s0 = 0.0f;
        if (nn == s_src[b + 1]) s1 = 0.0f;
        *(float2*)(g_sig + nn * BS + b) = make_float2(s0, s1);
    }
}

// ---------------------------------------------------------------------------
// edge: per-block smem relation->batch bitmask (replaces the prep kernel and
// turns the per-edge mask lookup into an LDS). For each edge, if its relation
// matches any batch relation, gather sig[head][b] and atomic scatter-add onto
// out[b][tail]. ~93% of edges match nothing and exit after one smem load.
// ---------------------------------------------------------------------------
__global__ void __launch_bounds__(256) edge_kernel(
    const int* __restrict__ heads,
    const int* __restrict__ tails,
    const int* __restrict__ rels,
    const int* __restrict__ relation_ids,
    float*     __restrict__ out)
{
    __shared__ unsigned s_mask[N_REL];

    const int tid = threadIdx.x;
    if (tid < N_REL) {
        unsigned m = 0;
        #pragma unroll
        for (int b = 0; b < BS; b++)
            m |= (relation_ids[b] == tid) ? (1u << b) : 0u;
        s_mask[tid] = m;
    }
    __syncthreads();

    const int i    = blockIdx.x * 256 + tid;
    const int base = i * 4;

    auto process = [&](int h, int t, int r) {
        unsigned m = s_mask[r];
        while (m) {
            int b = __ffs(m) - 1;
            m &= m - 1;
            atomicAdd(out + b * N_ENT + t, g_sig[h * BS + b]);
        }
    };

    if (base + 4 <= M_EDGES) {
        int4 h4 = *(const int4*)(heads + base);
        int4 t4 = *(const int4*)(tails + base);
        int4 r4 = *(const int4*)(rels  + base);
        process(h4.x, t4.x, r4.x);
        process(h4.y, t4.y, r4.y);
        process(h4.z, t4.z, r4.z);
        process(h4.w, t4.w, r4.w);
    } else if (base < M_EDGES) {
        for (int k = base; k < M_EDGES; k++)
            process(heads[k], tails[k], rels[k]);
    }
}

// ---------------------------------------------------------------------------
extern "C" void kernel_launch(void* const* d_in, const int* in_sizes, int n_in,
                              void* d_out, int out_size) {
    const float* emb          = (const float*)d_in[0];
    const float* all_emb      = (const float*)d_in[1];
    const float* tail_r       = (const float*)d_in[2];
    const int*   source_idx   = (const int*)  d_in[3];
    const int*   relation_ids = (const int*)  d_in[4];
    const int*   heads        = (const int*)  d_in[5];
    const int*   tails        = (const int*)  d_in[6];
    const int*   edge_rels    = (const int*)  d_in[7];
    float*       out          = (float*)d_out;

    const int warps  = (N_ENT + NT - 1) / NT;      // 3636
    const int blocks = (warps + 7) / 8;            // 455
    dist_kernel<<<blocks, 256>>>(emb, all_emb, tail_r, source_idx,
                                 relation_ids, out);

    const int ethreads = (M_EDGES + 3) / 4;        // 68029
    const int eblocks  = (ethreads + 255) / 256;   // 266
    edge_kernel<<<eblocks, 256>>>(heads, tails, edge_rels, relation_ids, out);
}